// round 4
// baseline (speedup 1.0000x reference)
#include <cuda_runtime.h>
#include <math.h>

constexpr int Nn = 100000;
constexpr int Ee = 1600000;
constexpr int SCAN_TILE = 1024;
constexpr int NTILES = (Nn + SCAN_TILE - 1) / SCAN_TILE;  // 98

__device__ float d_node[Nn * 64];
__device__ float d_agg[Nn * 64];
__device__ float d_norm[Ee];       // raw edge weight (pre-norm)
__device__ float d_dis[Nn];        // degree -> deg^-0.5 (in place)
__device__ float d_selfnorm[Nn];   // dis[i]^2
__device__ int d_cnt[Nn];
__device__ int d_off[Nn + 1];
__device__ int d_cur[Nn];
__device__ int d_tile[NTILES];
__device__ int d_csr_src[Ee];
__device__ float d_csr_w[Ee];      // fully normalized weight

__device__ __forceinline__ float leaky(float v, float s) {
    return v > 0.0f ? v : s * v;
}

// ---------------------------------------------------------------------------
__global__ void init_kernel() {
    int i = blockIdx.x * blockDim.x + threadIdx.x;
    if (i < Nn) { d_dis[i] = 1.0f; d_cnt[i] = 0; }
}

// ---------------------------------------------------------------------------
// Edge MLP + degree accumulation + CSR count (fused).
__global__ void edge_kernel(const float4* __restrict__ ea,
                            const int* __restrict__ ei,
                            const float* __restrict__ W1,
                            const float* __restrict__ b1,
                            const float* __restrict__ W2,
                            const float* __restrict__ b2) {
    __shared__ float sW1[64];
    __shared__ float sb1[16];
    __shared__ float sW2[16];
    __shared__ float sb2;
    int t = threadIdx.x;
    if (t < 64) sW1[t] = W1[t];
    if (t < 16) sb1[t] = b1[t];
    if (t >= 64 && t < 80) sW2[t - 64] = W2[t - 64];
    if (t == 80) sb2 = b2[0];
    __syncthreads();

    int e = blockIdx.x * blockDim.x + t;
    if (e >= Ee) return;
    float4 a = ea[e];
    float a0 = isnan(a.x) ? 0.0f : a.x;
    float a1 = isnan(a.y) ? 0.0f : a.y;
    float a2 = isnan(a.z) ? 0.0f : a.z;
    float a3 = isnan(a.w) ? 0.0f : a.w;

    float s = sb2;
#pragma unroll
    for (int j = 0; j < 16; j++) {
        float v = a0 * sW1[j] + a1 * sW1[16 + j] + a2 * sW1[32 + j] +
                  a3 * sW1[48 + j] + sb1[j];
        v = leaky(v, 0.2f);
        s += v * sW2[j];
    }
    float ew = leaky(s, 0.005f);
    d_norm[e] = ew;
    int col = ei[Ee + e];
    atomicAdd(&d_dis[col], ew);
    atomicAdd(&d_cnt[col], 1);
}

// ---------------------------------------------------------------------------
__global__ void dis_kernel() {
    int i = blockIdx.x * blockDim.x + threadIdx.x;
    if (i >= Nn) return;
    float d = d_dis[i];
    float r = rsqrtf(d);
    if (isinf(r)) r = 0.0f;
    d_dis[i] = r;
    d_selfnorm[i] = r * r;
}

// ---------------------------------------------------------------------------
// 3-kernel exclusive scan of d_cnt -> d_off, d_cur.
__global__ void scan1_kernel() {
    __shared__ int sh[SCAN_TILE];
    int tid = threadIdx.x;
    int i = blockIdx.x * SCAN_TILE + tid;
    int v = (i < Nn) ? d_cnt[i] : 0;
    sh[tid] = v;
    __syncthreads();
#pragma unroll
    for (int s = 1; s < SCAN_TILE; s <<= 1) {
        int add = (tid >= s) ? sh[tid - s] : 0;
        __syncthreads();
        sh[tid] += add;
        __syncthreads();
    }
    if (i < Nn) d_off[i] = sh[tid];  // inclusive, tile-local (temp)
    if (tid == SCAN_TILE - 1) d_tile[blockIdx.x] = sh[tid];
}

__global__ void scan2_kernel() {
    if (threadIdx.x == 0 && blockIdx.x == 0) {
        int run = 0;
        for (int b = 0; b < NTILES; b++) {
            int s = d_tile[b];
            d_tile[b] = run;
            run += s;
        }
        d_off[Nn] = Ee;
    }
}

__global__ void scan3_kernel() {
    int i = blockIdx.x * blockDim.x + threadIdx.x;
    if (i >= Nn) return;
    int excl = d_off[i] - d_cnt[i] + d_tile[i / SCAN_TILE];
    d_off[i] = excl;
    d_cur[i] = excl;
}

// ---------------------------------------------------------------------------
// CSR fill + norm fusion: csr_w = dis[row] * ew * dis[col].
__global__ void fill_kernel(const int* __restrict__ ei) {
    int e = blockIdx.x * blockDim.x + threadIdx.x;
    if (e >= Ee) return;
    int row = ei[e];
    int col = ei[Ee + e];
    int pos = atomicAdd(&d_cur[col], 1);
    d_csr_src[pos] = row;
    d_csr_w[pos] = d_dis[row] * d_norm[e] * d_dis[col];
}

// ---------------------------------------------------------------------------
// Node MLP stage 1: x[N,7] -> leaky(@Wn1+bn1, 0.2) -> d_agg (as temp)
__global__ void node1_kernel(const float* __restrict__ x,
                             const float* __restrict__ W1,
                             const float* __restrict__ b1) {
    __shared__ float sW[7 * 64];
    __shared__ float sb[64];
    for (int i = threadIdx.x; i < 448; i += blockDim.x) sW[i] = W1[i];
    if (threadIdx.x < 64) sb[threadIdx.x] = b1[threadIdx.x];
    __syncthreads();

    int r = blockIdx.x * blockDim.x + threadIdx.x;
    if (r >= Nn) return;
    float xi[7];
#pragma unroll
    for (int i = 0; i < 7; i++) {
        float v = x[r * 7 + i];
        xi[i] = isnan(v) ? 0.0f : v;
    }
    float4* outp = reinterpret_cast<float4*>(d_agg) + (size_t)r * 16;
#pragma unroll
    for (int j4 = 0; j4 < 16; j4++) {
        float o[4];
#pragma unroll
        for (int c = 0; c < 4; c++) {
            int j = j4 * 4 + c;
            float v = sb[j];
#pragma unroll
            for (int i = 0; i < 7; i++) v += xi[i] * sW[i * 64 + j];
            o[c] = leaky(v, 0.2f);
        }
        outp[j4] = make_float4(o[0], o[1], o[2], o[3]);
    }
}

// ---------------------------------------------------------------------------
// 64x64 GEMM + bias + leaky using packed fma.rn.f32x2 (node MLP / post MLP).
template <bool IN_AGG>
__global__ void __launch_bounds__(256) gemm64_kernel(const float* __restrict__ W,
                                                     const float* __restrict__ b,
                                                     float slope) {
    __shared__ float sW[4096];
    __shared__ float sb[64];
    {
        const float4* W4 = reinterpret_cast<const float4*>(W);
        float4* sW4 = reinterpret_cast<float4*>(sW);
        for (int i = threadIdx.x; i < 1024; i += 256) sW4[i] = W4[i];
        if (threadIdx.x < 64) sb[threadIdx.x] = b[threadIdx.x];
    }
    __syncthreads();

    int r = blockIdx.x * 256 + threadIdx.x;
    if (r >= Nn) return;

    const float* inbase = IN_AGG ? d_agg : d_node;
    const float4* inp = reinterpret_cast<const float4*>(inbase + (size_t)r * 64);

    unsigned long long acc[32];
#pragma unroll
    for (int j = 0; j < 32; j++) {
        asm("mov.b64 %0, {%1, %2};"
            : "=l"(acc[j]) : "f"(sb[2 * j]), "f"(sb[2 * j + 1]));
    }

#pragma unroll 4
    for (int k4 = 0; k4 < 16; k4++) {
        float4 x = inp[k4];
#pragma unroll
        for (int kk = 0; kk < 4; kk++) {
            float xk = (kk == 0) ? x.x : (kk == 1) ? x.y : (kk == 2) ? x.z : x.w;
            unsigned long long xx;
            asm("mov.b64 %0, {%1, %1};" : "=l"(xx) : "f"(xk));
            const ulonglong2* wr = reinterpret_cast<const ulonglong2*>(
                sW + (k4 * 4 + kk) * 64);
#pragma unroll
            for (int j2 = 0; j2 < 16; j2++) {
                ulonglong2 wp = wr[j2];
                asm("fma.rn.f32x2 %0, %1, %2, %0;"
                    : "+l"(acc[2 * j2]) : "l"(xx), "l"(wp.x));
                asm("fma.rn.f32x2 %0, %1, %2, %0;"
                    : "+l"(acc[2 * j2 + 1]) : "l"(xx), "l"(wp.y));
            }
        }
    }

    float* outbase = IN_AGG ? d_node : d_agg;
    float4* outp = reinterpret_cast<float4*>(outbase + (size_t)r * 64);
#pragma unroll
    for (int j4 = 0; j4 < 16; j4++) {
        float o0, o1, o2, o3;
        asm("mov.b64 {%0, %1}, %2;" : "=f"(o0), "=f"(o1) : "l"(acc[2 * j4]));
        asm("mov.b64 {%0, %1}, %2;" : "=f"(o2), "=f"(o3) : "l"(acc[2 * j4 + 1]));
        outp[j4] = make_float4(leaky(o0, slope), leaky(o1, slope),
                               leaky(o2, slope), leaky(o3, slope));
    }
}

// ---------------------------------------------------------------------------
// FUSED GCN layer: one warp per destination node.
//   1. gather: acc = selfnorm[n]*in[n] + sum_e w_e * in[src_e]   (float2/lane)
//   2. in-warp GEMM: out = leaky(acc @ W + b) via shfl broadcast + fma.f32x2
//   3. store out row directly (ping-pong buffers, SWAP selects direction)
// GEMM issue work hides under the gather's L2-bound latency on other warps.
template <bool SWAP>  // false: in=d_node out=d_agg ; true: in=d_agg out=d_node
__global__ void __launch_bounds__(256) layer_kernel(const float* __restrict__ W,
                                                    const float* __restrict__ b) {
    __shared__ float sW[4096];
    __shared__ float sb[64];
    {
        const float4* W4 = reinterpret_cast<const float4*>(W);
        float4* sW4 = reinterpret_cast<float4*>(sW);
        for (int i = threadIdx.x; i < 1024; i += 256) sW4[i] = W4[i];
        if (threadIdx.x < 64) sb[threadIdx.x] = b[threadIdx.x];
    }
    __syncthreads();

    int warp = (blockIdx.x * blockDim.x + threadIdx.x) >> 5;
    if (warp >= Nn) return;
    int lane = threadIdx.x & 31;

    const float2* nd =
        reinterpret_cast<const float2*>(SWAP ? d_agg : d_node);

    // ---- gather ----
    float sn = d_selfnorm[warp];
    float2 self = nd[(size_t)warp * 32 + lane];
    float accx = self.x * sn, accy = self.y * sn;

    int i = d_off[warp];
    int end = d_off[warp + 1];
    for (; i + 4 <= end; i += 4) {
        int s0 = __ldg(&d_csr_src[i + 0]);
        int s1 = __ldg(&d_csr_src[i + 1]);
        int s2 = __ldg(&d_csr_src[i + 2]);
        int s3 = __ldg(&d_csr_src[i + 3]);
        float w0 = __ldg(&d_csr_w[i + 0]);
        float w1 = __ldg(&d_csr_w[i + 1]);
        float w2 = __ldg(&d_csr_w[i + 2]);
        float w3 = __ldg(&d_csr_w[i + 3]);
        float2 v0 = nd[(size_t)s0 * 32 + lane];
        float2 v1 = nd[(size_t)s1 * 32 + lane];
        float2 v2 = nd[(size_t)s2 * 32 + lane];
        float2 v3 = nd[(size_t)s3 * 32 + lane];
        accx += v0.x * w0; accy += v0.y * w0;
        accx += v1.x * w1; accy += v1.y * w1;
        accx += v2.x * w2; accy += v2.y * w2;
        accx += v3.x * w3; accy += v3.y * w3;
    }
    for (; i < end; i++) {
        int s = __ldg(&d_csr_src[i]);
        float w = __ldg(&d_csr_w[i]);
        float2 v = nd[(size_t)s * 32 + lane];
        accx += v.x * w; accy += v.y * w;
    }

    // ---- in-warp 64x64 GEMM: lane owns output cols 2*lane, 2*lane+1 ----
    unsigned long long out;
    asm("mov.b64 %0, {%1, %2};"
        : "=l"(out) : "f"(sb[2 * lane]), "f"(sb[2 * lane + 1]));

    const unsigned long long* sW8 =
        reinterpret_cast<const unsigned long long*>(sW) + lane;  // +2*lane floats

#pragma unroll
    for (int l = 0; l < 32; l++) {
        float ax = __shfl_sync(0xFFFFFFFFu, accx, l);
        float ay = __shfl_sync(0xFFFFFFFFu, accy, l);
        unsigned long long axx, ayy;
        asm("mov.b64 %0, {%1, %1};" : "=l"(axx) : "f"(ax));
        asm("mov.b64 %0, {%1, %1};" : "=l"(ayy) : "f"(ay));
        unsigned long long w0 = sW8[(2 * l) * 32];
        unsigned long long w1 = sW8[(2 * l + 1) * 32];
        asm("fma.rn.f32x2 %0, %1, %2, %0;" : "+l"(out) : "l"(axx), "l"(w0));
        asm("fma.rn.f32x2 %0, %1, %2, %0;" : "+l"(out) : "l"(ayy), "l"(w1));
    }

    float o0, o1;
    asm("mov.b64 {%0, %1}, %2;" : "=f"(o0), "=f"(o1) : "l"(out));
    float2* outbuf = reinterpret_cast<float2*>(SWAP ? d_node : d_agg);
    outbuf[(size_t)warp * 32 + lane] =
        make_float2(leaky(o0, 0.2f), leaky(o1, 0.2f));
}

// ---------------------------------------------------------------------------
__global__ void final_kernel(const float* __restrict__ Wr,
                             const float* __restrict__ br,
                             float* __restrict__ out) {
    __shared__ float sW[256];
    __shared__ float sb[4];
    if (threadIdx.x < 256) sW[threadIdx.x] = Wr[threadIdx.x];
    if (threadIdx.x < 4) sb[threadIdx.x] = br[threadIdx.x];
    __syncthreads();

    int r = blockIdx.x * blockDim.x + threadIdx.x;
    if (r >= Nn) return;
    const float4* inp = reinterpret_cast<const float4*>(d_node + (size_t)r * 64);
    float acc[4] = {sb[0], sb[1], sb[2], sb[3]};
#pragma unroll
    for (int k4 = 0; k4 < 16; k4++) {
        float4 x = inp[k4];
#pragma unroll
        for (int kk = 0; kk < 4; kk++) {
            float xk = (kk == 0) ? x.x : (kk == 1) ? x.y : (kk == 2) ? x.z : x.w;
            const float* wr = sW + (k4 * 4 + kk) * 4;
            acc[0] += xk * wr[0];
            acc[1] += xk * wr[1];
            acc[2] += xk * wr[2];
            acc[3] += xk * wr[3];
        }
    }
    reinterpret_cast<float4*>(out)[r] = make_float4(acc[0], acc[1], acc[2], acc[3]);
}

// ---------------------------------------------------------------------------
extern "C" void kernel_launch(void* const* d_in, const int* in_sizes, int n_in,
                              void* d_out, int out_size) {
    const float* x = (const float*)d_in[0];
    const int* ei = (const int*)d_in[1];
    const float* ea = (const float*)d_in[2];
    const float* Wn1 = (const float*)d_in[3];
    const float* bn1 = (const float*)d_in[4];
    const float* Wn2 = (const float*)d_in[5];
    const float* bn2 = (const float*)d_in[6];
    const float* We1 = (const float*)d_in[7];
    const float* be1 = (const float*)d_in[8];
    const float* We2 = (const float*)d_in[9];
    const float* be2 = (const float*)d_in[10];
    const float* Wg = (const float*)d_in[11];
    const float* bg = (const float*)d_in[12];
    const float* Wp1 = (const float*)d_in[13];
    const float* bp1 = (const float*)d_in[14];
    const float* Wp2 = (const float*)d_in[15];
    const float* bp2 = (const float*)d_in[16];
    const float* Wr = (const float*)d_in[17];
    const float* br = (const float*)d_in[18];

    const int NB = (Nn + 255) / 256;
    const int EB = (Ee + 255) / 256;
    const int GB = (Nn * 32 + 255) / 256;  // warp per node

    // gcn_norm + CSR build (norm fused into fill)
    init_kernel<<<NB, 256>>>();
    edge_kernel<<<EB, 256>>>((const float4*)ea, ei, We1, be1, We2, be2);
    dis_kernel<<<NB, 256>>>();
    scan1_kernel<<<NTILES, SCAN_TILE>>>();
    scan2_kernel<<<1, 32>>>();
    scan3_kernel<<<NB, 256>>>();
    fill_kernel<<<EB, 256>>>(ei);

    // node MLP: x -> d_agg (node1), d_agg -> d_node (gemm Wn2)
    node1_kernel<<<NB, 256>>>(x, Wn1, bn1);
    gemm64_kernel<true><<<NB, 256>>>(Wn2, bn2, 0.2f);

    // 8 fused GCN layers, ping-pong d_node <-> d_agg (ends in d_node)
    for (int i = 0; i < 8; i += 2) {
        layer_kernel<false><<<GB, 256>>>(Wg + i * 4096, bg + i * 64);
        layer_kernel<true><<<GB, 256>>>(Wg + (i + 1) * 4096, bg + (i + 1) * 64);
    }

    // post MLP
    gemm64_kernel<false><<<NB, 256>>>(Wp1, bp1, 0.2f);
    gemm64_kernel<true><<<NB, 256>>>(Wp2, bp2, 0.2f);
    final_kernel<<<NB, 256>>>(Wr, br, (float*)d_out);
}

// round 6
// speedup vs baseline: 1.2205x; 1.2205x over previous
#include <cuda_runtime.h>
#include <math.h>

constexpr int Nn = 100000;
constexpr int Ee = 1600000;
constexpr int SCAN_TILE = 1024;
constexpr int NTILES = (Nn + SCAN_TILE - 1) / SCAN_TILE;  // 98

__device__ float d_node[Nn * 64];
__device__ float d_agg[Nn * 64];
__device__ float d_norm[Ee];       // raw edge weight (pre-norm)
__device__ float d_dis[Nn];        // degree -> deg^-0.5 (in place)
__device__ float d_selfnorm[Nn];   // dis[i]^2
__device__ int d_cnt[Nn];
__device__ int d_off[Nn + 1];
__device__ int d_cur[Nn];
__device__ int d_tile[NTILES];
__device__ int d_csr_src[Ee];
__device__ float d_csr_w[Ee];      // fully normalized weight

__device__ __forceinline__ float leaky(float v, float s) {
    return v > 0.0f ? v : s * v;
}

// ---------------------------------------------------------------------------
__global__ void init_kernel() {
    int i = blockIdx.x * blockDim.x + threadIdx.x;
    if (i < Nn) { d_dis[i] = 1.0f; d_cnt[i] = 0; }
}

// ---------------------------------------------------------------------------
// Edge MLP + degree accumulation + CSR count (fused).
__global__ void edge_kernel(const float4* __restrict__ ea,
                            const int* __restrict__ ei,
                            const float* __restrict__ W1,
                            const float* __restrict__ b1,
                            const float* __restrict__ W2,
                            const float* __restrict__ b2) {
    __shared__ float sW1[64];
    __shared__ float sb1[16];
    __shared__ float sW2[16];
    __shared__ float sb2;
    int t = threadIdx.x;
    if (t < 64) sW1[t] = W1[t];
    if (t < 16) sb1[t] = b1[t];
    if (t >= 64 && t < 80) sW2[t - 64] = W2[t - 64];
    if (t == 80) sb2 = b2[0];
    __syncthreads();

    int e = blockIdx.x * blockDim.x + t;
    if (e >= Ee) return;
    float4 a = ea[e];
    float a0 = isnan(a.x) ? 0.0f : a.x;
    float a1 = isnan(a.y) ? 0.0f : a.y;
    float a2 = isnan(a.z) ? 0.0f : a.z;
    float a3 = isnan(a.w) ? 0.0f : a.w;

    float s = sb2;
#pragma unroll
    for (int j = 0; j < 16; j++) {
        float v = a0 * sW1[j] + a1 * sW1[16 + j] + a2 * sW1[32 + j] +
                  a3 * sW1[48 + j] + sb1[j];
        v = leaky(v, 0.2f);
        s += v * sW2[j];
    }
    float ew = leaky(s, 0.005f);
    d_norm[e] = ew;
    int col = ei[Ee + e];
    atomicAdd(&d_dis[col], ew);
    atomicAdd(&d_cnt[col], 1);
}

// ---------------------------------------------------------------------------
__global__ void dis_kernel() {
    int i = blockIdx.x * blockDim.x + threadIdx.x;
    if (i >= Nn) return;
    float d = d_dis[i];
    float r = rsqrtf(d);
    if (isinf(r)) r = 0.0f;
    d_dis[i] = r;
    d_selfnorm[i] = r * r;
}

// ---------------------------------------------------------------------------
// 3-kernel exclusive scan of d_cnt -> d_off, d_cur.
__global__ void scan1_kernel() {
    __shared__ int sh[SCAN_TILE];
    int tid = threadIdx.x;
    int i = blockIdx.x * SCAN_TILE + tid;
    int v = (i < Nn) ? d_cnt[i] : 0;
    sh[tid] = v;
    __syncthreads();
#pragma unroll
    for (int s = 1; s < SCAN_TILE; s <<= 1) {
        int add = (tid >= s) ? sh[tid - s] : 0;
        __syncthreads();
        sh[tid] += add;
        __syncthreads();
    }
    if (i < Nn) d_off[i] = sh[tid];  // inclusive, tile-local (temp)
    if (tid == SCAN_TILE - 1) d_tile[blockIdx.x] = sh[tid];
}

__global__ void scan2_kernel() {
    if (threadIdx.x == 0 && blockIdx.x == 0) {
        int run = 0;
        for (int b = 0; b < NTILES; b++) {
            int s = d_tile[b];
            d_tile[b] = run;
            run += s;
        }
        d_off[Nn] = Ee;
    }
}

__global__ void scan3_kernel() {
    int i = blockIdx.x * blockDim.x + threadIdx.x;
    if (i >= Nn) return;
    int excl = d_off[i] - d_cnt[i] + d_tile[i / SCAN_TILE];
    d_off[i] = excl;
    d_cur[i] = excl;
}

// ---------------------------------------------------------------------------
// CSR fill + norm fusion: csr_w = dis[row] * ew * dis[col].
__global__ void fill_kernel(const int* __restrict__ ei) {
    int e = blockIdx.x * blockDim.x + threadIdx.x;
    if (e >= Ee) return;
    int row = ei[e];
    int col = ei[Ee + e];
    int pos = atomicAdd(&d_cur[col], 1);
    d_csr_src[pos] = row;
    d_csr_w[pos] = d_dis[row] * d_norm[e] * d_dis[col];
}

// ---------------------------------------------------------------------------
// Node MLP stage 1: x[N,7] -> leaky(@Wn1+bn1, 0.2) -> d_agg (as temp)
__global__ void node1_kernel(const float* __restrict__ x,
                             const float* __restrict__ W1,
                             const float* __restrict__ b1) {
    __shared__ float sW[7 * 64];
    __shared__ float sb[64];
    for (int i = threadIdx.x; i < 448; i += blockDim.x) sW[i] = W1[i];
    if (threadIdx.x < 64) sb[threadIdx.x] = b1[threadIdx.x];
    __syncthreads();

    int r = blockIdx.x * blockDim.x + threadIdx.x;
    if (r >= Nn) return;
    float xi[7];
#pragma unroll
    for (int i = 0; i < 7; i++) {
        float v = x[r * 7 + i];
        xi[i] = isnan(v) ? 0.0f : v;
    }
    float4* outp = reinterpret_cast<float4*>(d_agg) + (size_t)r * 16;
#pragma unroll
    for (int j4 = 0; j4 < 16; j4++) {
        float o[4];
#pragma unroll
        for (int c = 0; c < 4; c++) {
            int j = j4 * 4 + c;
            float v = sb[j];
#pragma unroll
            for (int i = 0; i < 7; i++) v += xi[i] * sW[i * 64 + j];
            o[c] = leaky(v, 0.2f);
        }
        outp[j4] = make_float4(o[0], o[1], o[2], o[3]);
    }
}

// ---------------------------------------------------------------------------
// 64x64 GEMM + bias + leaky using packed fma.rn.f32x2 (proven round-3 form).
template <bool IN_AGG>
__global__ void __launch_bounds__(256) gemm64_kernel(const float* __restrict__ W,
                                                     const float* __restrict__ b,
                                                     float slope) {
    __shared__ float sW[4096];
    __shared__ float sb[64];
    {
        const float4* W4 = reinterpret_cast<const float4*>(W);
        float4* sW4 = reinterpret_cast<float4*>(sW);
        for (int i = threadIdx.x; i < 1024; i += 256) sW4[i] = W4[i];
        if (threadIdx.x < 64) sb[threadIdx.x] = b[threadIdx.x];
    }
    __syncthreads();

    int r = blockIdx.x * 256 + threadIdx.x;
    if (r >= Nn) return;

    const float* inbase = IN_AGG ? d_agg : d_node;
    const float4* inp = reinterpret_cast<const float4*>(inbase + (size_t)r * 64);

    unsigned long long acc[32];
#pragma unroll
    for (int j = 0; j < 32; j++) {
        asm("mov.b64 %0, {%1, %2};"
            : "=l"(acc[j]) : "f"(sb[2 * j]), "f"(sb[2 * j + 1]));
    }

#pragma unroll 4
    for (int k4 = 0; k4 < 16; k4++) {
        float4 x = inp[k4];
#pragma unroll
        for (int kk = 0; kk < 4; kk++) {
            float xk = (kk == 0) ? x.x : (kk == 1) ? x.y : (kk == 2) ? x.z : x.w;
            unsigned long long xx;
            asm("mov.b64 %0, {%1, %1};" : "=l"(xx) : "f"(xk));
            const ulonglong2* wr = reinterpret_cast<const ulonglong2*>(
                sW + (k4 * 4 + kk) * 64);
#pragma unroll
            for (int j2 = 0; j2 < 16; j2++) {
                ulonglong2 wp = wr[j2];
                asm("fma.rn.f32x2 %0, %1, %2, %0;"
                    : "+l"(acc[2 * j2]) : "l"(xx), "l"(wp.x));
                asm("fma.rn.f32x2 %0, %1, %2, %0;"
                    : "+l"(acc[2 * j2 + 1]) : "l"(xx), "l"(wp.y));
            }
        }
    }

    float* outbase = IN_AGG ? d_node : d_agg;
    float4* outp = reinterpret_cast<float4*>(outbase + (size_t)r * 64);
#pragma unroll
    for (int j4 = 0; j4 < 16; j4++) {
        float o0, o1, o2, o3;
        asm("mov.b64 {%0, %1}, %2;" : "=f"(o0), "=f"(o1) : "l"(acc[2 * j4]));
        asm("mov.b64 {%0, %1}, %2;" : "=f"(o2), "=f"(o3) : "l"(acc[2 * j4 + 1]));
        outp[j4] = make_float4(leaky(o0, slope), leaky(o1, slope),
                               leaky(o2, slope), leaky(o3, slope));
    }
}

// ---------------------------------------------------------------------------
// CSR gather v2: one warp per destination node, HALF-WARP PER EDGE.
// Lanes 0-15 process even edge of a pair, lanes 16-31 the odd edge; each lane
// holds a float4 (16B) chunk -> one LDG.128 gathers two full 256B rows.
// Uniform csr loads are int2/float2 (1 wavefront each). Final cross-half
// combine: 4x shfl_xor(16) + add, then half-warp STG.128.
__global__ void __launch_bounds__(256) gather_kernel() {
    int warp = (blockIdx.x * blockDim.x + threadIdx.x) >> 5;
    if (warp >= Nn) return;
    int lane = threadIdx.x & 31;
    int chunk = lane & 15;          // float4 index within row
    bool hi = lane >= 16;           // upper half-warp -> odd edge of pair

    const float4* nd4 = reinterpret_cast<const float4*>(d_node);

    float4 acc = make_float4(0.f, 0.f, 0.f, 0.f);

    int i = d_off[warp];
    int end = d_off[warp + 1];

    // head: make i even so int2/float2 loads are 8B-aligned
    if ((i & 1) && i < end) {
        int s = __ldg(&d_csr_src[i]);
        float w = __ldg(&d_csr_w[i]);
        float4 v = nd4[(size_t)s * 16 + chunk];
        if (!hi) {  // only lower half accumulates (avoid double count)
            acc.x += v.x * w; acc.y += v.y * w;
            acc.z += v.z * w; acc.w += v.w * w;
        }
        i++;
    }
    // pair loop: 2 edges per iteration
#pragma unroll 4
    for (; i + 2 <= end; i += 2) {
        int2 s2 = *reinterpret_cast<const int2*>(d_csr_src + i);
        float2 w2 = *reinterpret_cast<const float2*>(d_csr_w + i);
        int s = hi ? s2.y : s2.x;
        float w = hi ? w2.y : w2.x;
        float4 v = nd4[(size_t)s * 16 + chunk];
        acc.x += v.x * w; acc.y += v.y * w;
        acc.z += v.z * w; acc.w += v.w * w;
    }
    // tail: one leftover edge
    if (i < end) {
        int s = __ldg(&d_csr_src[i]);
        float w = __ldg(&d_csr_w[i]);
        float4 v = nd4[(size_t)s * 16 + chunk];
        if (!hi) {
            acc.x += v.x * w; acc.y += v.y * w;
            acc.z += v.z * w; acc.w += v.w * w;
        }
    }

    // combine halves: lower lanes end with full sum
    acc.x += __shfl_xor_sync(0xFFFFFFFFu, acc.x, 16);
    acc.y += __shfl_xor_sync(0xFFFFFFFFu, acc.y, 16);
    acc.z += __shfl_xor_sync(0xFFFFFFFFu, acc.z, 16);
    acc.w += __shfl_xor_sync(0xFFFFFFFFu, acc.w, 16);

    if (!hi) {
        // self-loop term + store
        float sn = d_selfnorm[warp];
        float4 self = nd4[(size_t)warp * 16 + chunk];
        acc.x += self.x * sn; acc.y += self.y * sn;
        acc.z += self.z * sn; acc.w += self.w * sn;
        reinterpret_cast<float4*>(d_agg)[(size_t)warp * 16 + chunk] = acc;
    }
}

// ---------------------------------------------------------------------------
__global__ void final_kernel(const float* __restrict__ Wr,
                             const float* __restrict__ br,
                             float* __restrict__ out) {
    __shared__ float sW[256];
    __shared__ float sb[4];
    if (threadIdx.x < 256) sW[threadIdx.x] = Wr[threadIdx.x];
    if (threadIdx.x < 4) sb[threadIdx.x] = br[threadIdx.x];
    __syncthreads();

    int r = blockIdx.x * blockDim.x + threadIdx.x;
    if (r >= Nn) return;
    const float4* inp = reinterpret_cast<const float4*>(d_node + (size_t)r * 64);
    float acc[4] = {sb[0], sb[1], sb[2], sb[3]};
#pragma unroll
    for (int k4 = 0; k4 < 16; k4++) {
        float4 x = inp[k4];
#pragma unroll
        for (int kk = 0; kk < 4; kk++) {
            float xk = (kk == 0) ? x.x : (kk == 1) ? x.y : (kk == 2) ? x.z : x.w;
            const float* wr = sW + (k4 * 4 + kk) * 4;
            acc[0] += xk * wr[0];
            acc[1] += xk * wr[1];
            acc[2] += xk * wr[2];
            acc[3] += xk * wr[3];
        }
    }
    reinterpret_cast<float4*>(out)[r] = make_float4(acc[0], acc[1], acc[2], acc[3]);
}

// ---------------------------------------------------------------------------
extern "C" void kernel_launch(void* const* d_in, const int* in_sizes, int n_in,
                              void* d_out, int out_size) {
    const float* x = (const float*)d_in[0];
    const int* ei = (const int*)d_in[1];
    const float* ea = (const float*)d_in[2];
    const float* Wn1 = (const float*)d_in[3];
    const float* bn1 = (const float*)d_in[4];
    const float* Wn2 = (const float*)d_in[5];
    const float* bn2 = (const float*)d_in[6];
    const float* We1 = (const float*)d_in[7];
    const float* be1 = (const float*)d_in[8];
    const float* We2 = (const float*)d_in[9];
    const float* be2 = (const float*)d_in[10];
    const float* Wg = (const float*)d_in[11];
    const float* bg = (const float*)d_in[12];
    const float* Wp1 = (const float*)d_in[13];
    const float* bp1 = (const float*)d_in[14];
    const float* Wp2 = (const float*)d_in[15];
    const float* bp2 = (const float*)d_in[16];
    const float* Wr = (const float*)d_in[17];
    const float* br = (const float*)d_in[18];

    const int NB = (Nn + 255) / 256;
    const int EB = (Ee + 255) / 256;
    const int GB = (Nn * 32 + 255) / 256;  // warp per node

    // gcn_norm + CSR build (norm fused into fill)
    init_kernel<<<NB, 256>>>();
    edge_kernel<<<EB, 256>>>((const float4*)ea, ei, We1, be1, We2, be2);
    dis_kernel<<<NB, 256>>>();
    scan1_kernel<<<NTILES, SCAN_TILE>>>();
    scan2_kernel<<<1, 32>>>();
    scan3_kernel<<<NB, 256>>>();
    fill_kernel<<<EB, 256>>>(ei);

    // node MLP
    node1_kernel<<<NB, 256>>>(x, Wn1, bn1);
    gemm64_kernel<true><<<NB, 256>>>(Wn2, bn2, 0.2f);

    // 8 GCN layers: vectorized gather, then GEMM+bias+leaky
    for (int i = 0; i < 8; i++) {
        gather_kernel<<<GB, 256>>>();
        gemm64_kernel<true><<<NB, 256>>>(Wg + i * 4096, bg + i * 64, 0.2f);
    }

    // post MLP
    gemm64_kernel<false><<<NB, 256>>>(Wp1, bp1, 0.2f);
    gemm64_kernel<true><<<NB, 256>>>(Wp2, bp2, 0.2f);
    final_kernel<<<NB, 256>>>(Wr, br, (float*)d_out);
}